// round 3
// baseline (speedup 1.0000x reference)
#include <cuda_runtime.h>
#include <math.h>

// RGAT: 4x GATv2 over 15552 independent 17-node graphs, C=128.
// Fully fused: one block owns GPB graphs, all layers run in smem.

namespace {

constexpr int J    = 17;
constexpr int C    = 128;
constexpr int GPB  = 3;            // graphs per block
constexpr int MROWS = GPB * J;     // 51
constexpr int MPAD  = 56;          // 8 warps * 7 rows
constexpr int NE   = 64;           // edges per graph
constexpr int NTH  = 256;
constexpr int NGRAPHS = 15552;     // B*T
constexpr int NBLOCKS = NGRAPHS / GPB;  // 5184

} // namespace

// Baked skeleton edges: base 32 + flipped 32 (matches reference _build_edges).
// __device__ constexpr: usable in device code, fully folded under #pragma unroll.
__device__ constexpr int ESRC[NE] = {
  0,0,0,1,1,2,2,3,4,4,5,5,6,7,7,8,8,8,8,9,9,10,11,11,12,12,13,14,14,15,15,16,
  1,4,7,0,2,1,3,2,0,5,4,6,5,0,8,7,9,11,14,8,10,9,8,12,11,13,12,8,15,14,16,15
};
__device__ constexpr int EDST[NE] = {
  1,4,7,0,2,1,3,2,0,5,4,6,5,0,8,7,9,11,14,8,10,9,8,12,11,13,12,8,15,14,16,15,
  0,0,0,1,1,2,2,3,4,4,5,5,6,7,7,8,8,8,8,9,9,10,11,11,12,12,13,14,14,15,15,16
};

// Runtime-indexable copies (dynamic indexing paths).
__device__ __constant__ int c_esrc[NE] = {
  0,0,0,1,1,2,2,3,4,4,5,5,6,7,7,8,8,8,8,9,9,10,11,11,12,12,13,14,14,15,15,16,
  1,4,7,0,2,1,3,2,0,5,4,6,5,0,8,7,9,11,14,8,10,9,8,12,11,13,12,8,15,14,16,15
};
__device__ __constant__ int c_edst[NE] = {
  1,4,7,0,2,1,3,2,0,5,4,6,5,0,8,7,9,11,14,8,10,9,8,12,11,13,12,8,15,14,16,15,
  0,0,0,1,1,2,2,3,4,4,5,5,6,7,7,8,8,8,8,9,9,10,11,11,12,12,13,14,14,15,15,16
};

struct Smem {
  float Wl[C][C];          // 64 KB
  float Wr[C][C];          // 64 KB
  float h [MPAD][C];       // 28 KB (rows >= MROWS zero-padded)
  float xl[MPAD][C];       // 28 KB
  float xr[MPAD][C];       // 28 KB
  float bl[C], br[C], att[C], bias[C], ln_g[C], ln_b[C];
  float logit[GPB * NE];
  float aw   [GPB * NE];
  float mx [GPB * J];
  float den[GPB * J];
};

__global__ __launch_bounds__(NTH, 1)
void rgat_kernel(const float* __restrict__ x,
                 const float* __restrict__ ln_gamma,
                 const float* __restrict__ ln_beta,
                 const float* __restrict__ alpha,
                 const float* __restrict__ Wl,
                 const float* __restrict__ bl,
                 const float* __restrict__ Wr,
                 const float* __restrict__ br,
                 const float* __restrict__ att,
                 const float* __restrict__ bias,
                 float* __restrict__ out)
{
  extern __shared__ char smem_raw[];
  Smem& s = *reinterpret_cast<Smem*>(smem_raw);

  const int t    = threadIdx.x;
  const int warp = t >> 5;
  const int lane = t & 31;
  const int node0 = blockIdx.x * MROWS;
  const float* xblk = x + (size_t)node0 * C;

  // ---- init: weights, vectors, zero pad rows ----
  {
    const float4* wl4 = reinterpret_cast<const float4*>(Wl);
    const float4* wr4 = reinterpret_cast<const float4*>(Wr);
    float4* sl4 = reinterpret_cast<float4*>(&s.Wl[0][0]);
    float4* sr4 = reinterpret_cast<float4*>(&s.Wr[0][0]);
    for (int i = t; i < C * C / 4; i += NTH) { sl4[i] = wl4[i]; sr4[i] = wr4[i]; }
  }
  for (int i = t; i < C; i += NTH) {
    s.bl[i] = bl[i];  s.br[i] = br[i];
    s.att[i] = att[i]; s.bias[i] = bias[i];
    s.ln_g[i] = ln_gamma[i]; s.ln_b[i] = ln_beta[i];
  }
  for (int i = t; i < (MPAD - MROWS) * C; i += NTH)
    s.h[MROWS + i / C][i % C] = 0.0f;

  const float sgate = 1.0f / (1.0f + expf(-alpha[0]));
  const float oms   = 1.0f - sgate;

  __syncthreads();

  // ---- LayerNorm: one warp per row ----
  for (int r = warp; r < MROWS; r += 8) {
    float v0 = xblk[r * C + lane];
    float v1 = xblk[r * C + lane + 32];
    float v2 = xblk[r * C + lane + 64];
    float v3 = xblk[r * C + lane + 96];
    float sum = v0 + v1 + v2 + v3;
    float sq  = v0 * v0 + v1 * v1 + v2 * v2 + v3 * v3;
    #pragma unroll
    for (int o = 16; o > 0; o >>= 1) {
      sum += __shfl_xor_sync(0xffffffffu, sum, o);
      sq  += __shfl_xor_sync(0xffffffffu, sq,  o);
    }
    float mu  = sum * (1.0f / C);
    float var = sq * (1.0f / C) - mu * mu;
    float inv = rsqrtf(var + 1e-5f);
    s.h[r][lane     ] = (v0 - mu) * inv * s.ln_g[lane     ] + s.ln_b[lane     ];
    s.h[r][lane + 32] = (v1 - mu) * inv * s.ln_g[lane + 32] + s.ln_b[lane + 32];
    s.h[r][lane + 64] = (v2 - mu) * inv * s.ln_g[lane + 64] + s.ln_b[lane + 64];
    s.h[r][lane + 96] = (v3 - mu) * inv * s.ln_g[lane + 96] + s.ln_b[lane + 96];
  }

  // GEMM tiling: 8 row-groups (warps) x 7 rows; 4 consecutive cols / thread.
  const int r0 = warp * 7;
  const int j4 = (t & 31) * 4;

  for (int layer = 0; layer < 4; ++layer) {
    __syncthreads();   // h ready (LN or previous aggregation)

    // ---- fused xl = h@Wl + bl, xr = h@Wr + br ----
    float accL[7][4], accR[7][4];
    #pragma unroll
    for (int i = 0; i < 7; ++i)
      #pragma unroll
      for (int q = 0; q < 4; ++q) {
        accL[i][q] = s.bl[j4 + q];
        accR[i][q] = s.br[j4 + q];
      }

    #pragma unroll 8
    for (int k = 0; k < C; ++k) {
      float4 wl = *reinterpret_cast<const float4*>(&s.Wl[k][j4]);
      float4 wr = *reinterpret_cast<const float4*>(&s.Wr[k][j4]);
      #pragma unroll
      for (int i = 0; i < 7; ++i) {
        float hv = s.h[r0 + i][k];
        accL[i][0] += hv * wl.x; accL[i][1] += hv * wl.y;
        accL[i][2] += hv * wl.z; accL[i][3] += hv * wl.w;
        accR[i][0] += hv * wr.x; accR[i][1] += hv * wr.y;
        accR[i][2] += hv * wr.z; accR[i][3] += hv * wr.w;
      }
    }
    #pragma unroll
    for (int i = 0; i < 7; ++i) {
      *reinterpret_cast<float4*>(&s.xl[r0 + i][j4]) =
          make_float4(accL[i][0], accL[i][1], accL[i][2], accL[i][3]);
      *reinterpret_cast<float4*>(&s.xr[r0 + i][j4]) =
          make_float4(accR[i][0], accR[i][1], accR[i][2], accR[i][3]);
    }
    __syncthreads();

    // ---- edge logits: att . leaky_relu(xl[src] + xr[dst]) ----
    for (int i = 0; i < 24; ++i) {          // 8 warps * 24 = 192 edges
      int eg = warp + 8 * i;
      int g = eg >> 6, e = eg & 63;
      int sn = g * J + c_esrc[e];
      int dn = g * J + c_edst[e];
      float acc = 0.0f;
      #pragma unroll
      for (int q = 0; q < 4; ++q) {
        int cc = lane + 32 * q;
        float v = s.xl[sn][cc] + s.xr[dn][cc];
        v = (v > 0.0f) ? v : 0.2f * v;
        acc += s.att[cc] * v;
      }
      #pragma unroll
      for (int o = 16; o > 0; o >>= 1)
        acc += __shfl_xor_sync(0xffffffffu, acc, o);
      if (lane == 0) s.logit[eg] = acc;
    }
    __syncthreads();

    // ---- segment softmax (max + denom per dst node) ----
    if (t < GPB * J) {
      int g = t / J, n = t % J;
      const float* lg = &s.logit[g * NE];
      float m = -1e30f;
      #pragma unroll
      for (int e = 0; e < NE; ++e)
        if (EDST[e] == n) m = fmaxf(m, lg[e]);
      float d = 0.0f;
      #pragma unroll
      for (int e = 0; e < NE; ++e)
        if (EDST[e] == n) d += expf(lg[e] - m);
      s.mx[t] = m; s.den[t] = d;
    }
    __syncthreads();
    if (t < GPB * NE) {
      int g = t >> 6, e = t & 63;
      int dn = g * J + c_edst[e];
      s.aw[t] = expf(s.logit[t] - s.mx[dn]) / s.den[dn];
    }
    __syncthreads();

    // ---- aggregation + residual gate ----
    for (int it = 0; it < 2; ++it) {
      int idx = t + it * NTH;
      if (idx < GPB * C) {                 // 384 (graph, channel) pairs
        int g = idx >> 7;
        int cc = idx & 127;
        float acc[J];
        #pragma unroll
        for (int n = 0; n < J; ++n) acc[n] = s.bias[cc];
        const float* ag = &s.aw[g * NE];
        #pragma unroll
        for (int e = 0; e < NE; ++e)
          acc[EDST[e]] += ag[e] * s.xl[g * J + ESRC[e]][cc];
        #pragma unroll
        for (int n = 0; n < J; ++n) {
          int r = g * J + n;
          float v = acc[n];
          if (layer > 0) v = oms * v + sgate * xblk[r * C + cc];
          s.h[r][cc] = v;
        }
      }
    }
    // loop-top __syncthreads orders h before next GEMM
  }

  __syncthreads();

  // ---- out = x + h ----
  const float4* x4 = reinterpret_cast<const float4*>(xblk);
  float4* o4 = reinterpret_cast<float4*>(out + (size_t)node0 * C);
  for (int i = t; i < MROWS * (C / 4); i += NTH) {
    int r = i >> 5, q = i & 31;
    float4 xv = x4[i];
    const float4 hv = *reinterpret_cast<const float4*>(&s.h[r][q * 4]);
    o4[i] = make_float4(xv.x + hv.x, xv.y + hv.y, xv.z + hv.z, xv.w + hv.w);
  }
}

extern "C" void kernel_launch(void* const* d_in, const int* in_sizes, int n_in,
                              void* d_out, int out_size)
{
  const float* x        = (const float*)d_in[0];
  const float* ln_gamma = (const float*)d_in[1];
  const float* ln_beta  = (const float*)d_in[2];
  const float* alpha    = (const float*)d_in[3];
  const float* Wl       = (const float*)d_in[4];
  const float* bl       = (const float*)d_in[5];
  const float* Wr       = (const float*)d_in[6];
  const float* br       = (const float*)d_in[7];
  const float* att      = (const float*)d_in[8];
  const float* bias     = (const float*)d_in[9];
  // d_in[10], d_in[11]: edge_src/edge_dst — structure is baked in as constants.
  (void)in_sizes; (void)n_in; (void)out_size;

  (void)cudaFuncSetAttribute(rgat_kernel,
                             cudaFuncAttributeMaxDynamicSharedMemorySize,
                             (int)sizeof(Smem));
  rgat_kernel<<<NBLOCKS, NTH, sizeof(Smem)>>>(
      x, ln_gamma, ln_beta, alpha, Wl, bl, Wr, br, att, bias, (float*)d_out);
}

// round 6
// speedup vs baseline: 1.1443x; 1.1443x over previous
#include <cuda_runtime.h>
#include <cuda_bf16.h>
#include <math.h>
#include <stdint.h>

// RGAT: 4x GATv2 over 15552 independent 17-node graphs, C=128.
// Fused per-block (3 graphs); GEMM core = mma.sync m16n8k16 bf16 (sm_80-class
// PTX -- compiles for plain sm_100 target), split hi/lo precision, fp32 accum.

namespace {
constexpr int J   = 17;
constexpr int C   = 128;
constexpr int GPB = 3;
constexpr int MROWS = GPB * J;           // 51
constexpr int MPAD  = 64;                // MMA M
constexpr int NE  = 64;
constexpr int NTH = 256;
constexpr int NGRAPHS = 15552;
constexpr int NBLOCKS = NGRAPHS / GPB;   // 5184
constexpr int MPADT = 53;                // xlT/xrT row stride (odd -> no conflicts)
}

__device__ constexpr int ESRC[NE] = {
  0,0,0,1,1,2,2,3,4,4,5,5,6,7,7,8,8,8,8,9,9,10,11,11,12,12,13,14,14,15,15,16,
  1,4,7,0,2,1,3,2,0,5,4,6,5,0,8,7,9,11,14,8,10,9,8,12,11,13,12,8,15,14,16,15
};
__device__ constexpr int EDST[NE] = {
  1,4,7,0,2,1,3,2,0,5,4,6,5,0,8,7,9,11,14,8,10,9,8,12,11,13,12,8,15,14,16,15,
  0,0,0,1,1,2,2,3,4,4,5,5,6,7,7,8,8,8,8,9,9,10,11,11,12,12,13,14,14,15,15,16
};
__device__ __constant__ int c_esrc[NE] = {
  0,0,0,1,1,2,2,3,4,4,5,5,6,7,7,8,8,8,8,9,9,10,11,11,12,12,13,14,14,15,15,16,
  1,4,7,0,2,1,3,2,0,5,4,6,5,0,8,7,9,11,14,8,10,9,8,12,11,13,12,8,15,14,16,15
};
__device__ __constant__ int c_edst[NE] = {
  1,4,7,0,2,1,3,2,0,5,4,6,5,0,8,7,9,11,14,8,10,9,8,12,11,13,12,8,15,14,16,15,
  0,0,0,1,1,2,2,3,4,4,5,5,6,7,7,8,8,8,8,9,9,10,11,11,12,12,13,14,14,15,15,16
};

struct Smem {
  __nv_bfloat16 Wlh[C*C];   // [k][n] swizzled, 32 KB each
  __nv_bfloat16 Wll[C*C];
  __nv_bfloat16 Wrh[C*C];
  __nv_bfloat16 Wrl[C*C];
  __nv_bfloat16 Ah[MPAD*C]; // [m][k] swizzled, 16 KB each
  __nv_bfloat16 Al[MPAD*C];
  float xlT[C][MPADT];      // 27136 B each
  float xrT[C][MPADT];
  float bl[C], br[C], att[C], bias[C];
  float logit[GPB*NE], aw[GPB*NE];
  float mx[MROWS], den[MROWS];
};

// ---------------- helpers ----------------
__device__ __forceinline__ uint32_t smem_u32(const void* p) {
  uint32_t a;
  asm("{ .reg .u64 t; cvta.to.shared.u64 t, %1; cvt.u32.u64 %0, t; }" : "=r"(a) : "l"(p));
  return a;
}
__device__ __forceinline__ void ldsm4(uint32_t* f, uint32_t a) {
  asm volatile("ldmatrix.sync.aligned.m8n8.x4.shared.b16 {%0,%1,%2,%3}, [%4];"
    : "=r"(f[0]),"=r"(f[1]),"=r"(f[2]),"=r"(f[3]) : "r"(a));
}
__device__ __forceinline__ void ldsm2t(uint32_t* f, uint32_t a) {
  asm volatile("ldmatrix.sync.aligned.m8n8.x2.trans.shared.b16 {%0,%1}, [%2];"
    : "=r"(f[0]),"=r"(f[1]) : "r"(a));
}
__device__ __forceinline__ void mma16816(float* d, const uint32_t* a, const uint32_t* b) {
  asm volatile("mma.sync.aligned.m16n8k16.row.col.f32.bf16.bf16.f32 "
    "{%0,%1,%2,%3}, {%4,%5,%6,%7}, {%8,%9}, {%0,%1,%2,%3};"
    : "+f"(d[0]),"+f"(d[1]),"+f"(d[2]),"+f"(d[3])
    : "r"(a[0]),"r"(a[1]),"r"(a[2]),"r"(a[3]), "r"(b[0]),"r"(b[1]));
}
// A tile byte offset: row m, col k. 256B rows, 16B chunks XOR-swizzled by m&7.
__device__ __forceinline__ uint32_t swzA(int m, int k) {
  return (uint32_t)(m*256 + ((((k>>3) ^ (m&7))<<4) | ((k&7)*2)));
}
__device__ __forceinline__ ushort bf16u(float v) {
  return __bfloat16_as_ushort(__float2bfloat16(v));
}

__global__ __launch_bounds__(NTH, 1)
void rgat_hmma_kernel(const float* __restrict__ x,
                      const float* __restrict__ ln_gamma,
                      const float* __restrict__ ln_beta,
                      const float* __restrict__ alpha,
                      const float* __restrict__ Wl,
                      const float* __restrict__ bl,
                      const float* __restrict__ Wr,
                      const float* __restrict__ br,
                      const float* __restrict__ att,
                      const float* __restrict__ bias,
                      float* __restrict__ out)
{
  extern __shared__ char raw[];
  uintptr_t pa = ((uintptr_t)raw + 1023) & ~(uintptr_t)1023;
  Smem& s = *reinterpret_cast<Smem*>(pa);

  const int t    = threadIdx.x;
  const int warp = t >> 5;
  const int lane = t & 31;
  const int node0 = blockIdx.x * MROWS;
  const float* xblk = x + (size_t)node0 * C;

  // ---- prologue: zero A tiles (pad rows must be finite), W tiles, vectors ----
  for (int i = t; i < MPAD*C/2; i += NTH) {
    reinterpret_cast<uint32_t*>(s.Ah)[i] = 0u;
    reinterpret_cast<uint32_t*>(s.Al)[i] = 0u;
  }
  for (int i = t; i < C*C/4; i += NTH) {
    int k = i >> 5, n4 = (i & 31) * 4;
    float4 vl = reinterpret_cast<const float4*>(Wl)[i];
    float4 vr = reinterpret_cast<const float4*>(Wr)[i];
    uint32_t off = (uint32_t)(k*256 + ((((n4>>3) ^ (k&7))<<4) | ((n4&7)*2)));
    ushort h0 = bf16u(vl.x), h1 = bf16u(vl.y), h2 = bf16u(vl.z), h3 = bf16u(vl.w);
    uint2 hp = make_uint2((uint32_t)h0 | ((uint32_t)h1 << 16),
                          (uint32_t)h2 | ((uint32_t)h3 << 16));
    uint2 lp = make_uint2(
      (uint32_t)bf16u(vl.x - __bfloat162float(__ushort_as_bfloat16(h0))) |
      ((uint32_t)bf16u(vl.y - __bfloat162float(__ushort_as_bfloat16(h1))) << 16),
      (uint32_t)bf16u(vl.z - __bfloat162float(__ushort_as_bfloat16(h2))) |
      ((uint32_t)bf16u(vl.w - __bfloat162float(__ushort_as_bfloat16(h3))) << 16));
    *reinterpret_cast<uint2*>(reinterpret_cast<char*>(s.Wlh) + off) = hp;
    *reinterpret_cast<uint2*>(reinterpret_cast<char*>(s.Wll) + off) = lp;
    h0 = bf16u(vr.x); h1 = bf16u(vr.y); h2 = bf16u(vr.z); h3 = bf16u(vr.w);
    hp = make_uint2((uint32_t)h0 | ((uint32_t)h1 << 16),
                    (uint32_t)h2 | ((uint32_t)h3 << 16));
    lp = make_uint2(
      (uint32_t)bf16u(vr.x - __bfloat162float(__ushort_as_bfloat16(h0))) |
      ((uint32_t)bf16u(vr.y - __bfloat162float(__ushort_as_bfloat16(h1))) << 16),
      (uint32_t)bf16u(vr.z - __bfloat162float(__ushort_as_bfloat16(h2))) |
      ((uint32_t)bf16u(vr.w - __bfloat162float(__ushort_as_bfloat16(h3))) << 16));
    *reinterpret_cast<uint2*>(reinterpret_cast<char*>(s.Wrh) + off) = hp;
    *reinterpret_cast<uint2*>(reinterpret_cast<char*>(s.Wrl) + off) = lp;
  }
  for (int i = t; i < C; i += NTH) {
    s.bl[i] = bl[i]; s.br[i] = br[i]; s.att[i] = att[i]; s.bias[i] = bias[i];
  }
  const float sg  = 1.0f / (1.0f + expf(-alpha[0]));
  const float oms = 1.0f - sg;

  // ---- LayerNorm -> Ah/Al (hi/lo bf16) ----
  for (int r = warp; r < MROWS; r += 8) {
    float v0 = xblk[r*C + lane],      v1 = xblk[r*C + lane + 32];
    float v2 = xblk[r*C + lane + 64], v3 = xblk[r*C + lane + 96];
    float sum = v0+v1+v2+v3, sq = v0*v0+v1*v1+v2*v2+v3*v3;
    #pragma unroll
    for (int o = 16; o > 0; o >>= 1) {
      sum += __shfl_xor_sync(0xffffffffu, sum, o);
      sq  += __shfl_xor_sync(0xffffffffu, sq,  o);
    }
    float mu = sum * (1.0f/C);
    float inv = rsqrtf(sq * (1.0f/C) - mu*mu + 1e-5f);
    #pragma unroll
    for (int q = 0; q < 4; ++q) {
      int cc = lane + 32*q;
      float vv = (q==0?v0:q==1?v1:q==2?v2:v3);
      float hval = (vv-mu)*inv*ln_gamma[cc] + ln_beta[cc];
      ushort hi = bf16u(hval);
      *reinterpret_cast<ushort*>(reinterpret_cast<char*>(s.Ah) + swzA(r, cc)) = hi;
      *reinterpret_cast<ushort*>(reinterpret_cast<char*>(s.Al) + swzA(r, cc)) =
          bf16u(hval - __bfloat162float(__ushort_as_bfloat16(hi)));
    }
  }

  const uint32_t aAh  = smem_u32(s.Ah),  aAl  = smem_u32(s.Al);
  const uint32_t aWlh = smem_u32(s.Wlh), aWll = smem_u32(s.Wll);
  const uint32_t aWrh = smem_u32(s.Wrh), aWrl = smem_u32(s.Wrl);
  // lane decomposition for ldmatrix addressing
  const int rA = lane & 7;
  const int rowOffA = ((lane>>3)&1)*8 + rA;   // matrix row offset within m16
  const int chOffA  = (lane>>4);              // k-chunk offset (0/1)
  const int rB  = lane & 7;
  const int miB = (lane>>3)&1;
  // epilogue lane mapping
  const int eM = lane >> 2;
  const int eN = 2*(lane & 3);

  #pragma unroll 1
  for (int layer = 0; layer < 4; ++layer) {
    __syncthreads();   // Ah/Al ready (LN or previous aggregation)

    float accL[4][2][4];
    float accR[4][2][4];
    #pragma unroll
    for (int mt = 0; mt < 4; ++mt)
      #pragma unroll
      for (int nt = 0; nt < 2; ++nt)
        #pragma unroll
        for (int q = 0; q < 4; ++q) { accL[mt][nt][q] = 0.f; accR[mt][nt][q] = 0.f; }

    #pragma unroll
    for (int ks = 0; ks < 8; ++ks) {
      uint32_t fAh[4][4], fAl[4][4];
      #pragma unroll
      for (int mt = 0; mt < 4; ++mt) {
        uint32_t ar = (uint32_t)((mt*16 + rowOffA)*256 + (((2*ks + chOffA) ^ rA)<<4));
        ldsm4(fAh[mt], aAh + ar);
        ldsm4(fAl[mt], aAl + ar);
      }
      #pragma unroll
      for (int nt = 0; nt < 2; ++nt) {
        int n0 = warp*16 + nt*8;
        uint32_t boff = (uint32_t)((ks*16 + miB*8 + rB)*256 + (((n0>>3) ^ rB)<<4));
        uint32_t bh[2], blo[2];
        ldsm2t(bh,  aWlh + boff);
        ldsm2t(blo, aWll + boff);
        #pragma unroll
        for (int mt = 0; mt < 4; ++mt) {
          mma16816(accL[mt][nt], fAh[mt], bh);
          mma16816(accL[mt][nt], fAl[mt], bh);
          mma16816(accL[mt][nt], fAh[mt], blo);
        }
        ldsm2t(bh,  aWrh + boff);
        ldsm2t(blo, aWrl + boff);
        #pragma unroll
        for (int mt = 0; mt < 4; ++mt) {
          mma16816(accR[mt][nt], fAh[mt], bh);
          mma16816(accR[mt][nt], fAl[mt], bh);
          mma16816(accR[mt][nt], fAh[mt], blo);
        }
      }
    }

    // ---- epilogue: fragments -> xlT/xrT (+bias) ----
    #pragma unroll
    for (int mt = 0; mt < 4; ++mt)
      #pragma unroll
      for (int nt = 0; nt < 2; ++nt) {
        int n0 = warp*16 + nt*8 + eN;
        int m0 = mt*16 + eM;
        float b0 = s.bl[n0], b1 = s.bl[n0+1];
        float c0 = s.br[n0], c1 = s.br[n0+1];
        if (m0 < MROWS) {
          s.xlT[n0  ][m0] = accL[mt][nt][0] + b0;
          s.xlT[n0+1][m0] = accL[mt][nt][1] + b1;
          s.xrT[n0  ][m0] = accR[mt][nt][0] + c0;
          s.xrT[n0+1][m0] = accR[mt][nt][1] + c1;
        }
        if (m0+8 < MROWS) {
          s.xlT[n0  ][m0+8] = accL[mt][nt][2] + b0;
          s.xlT[n0+1][m0+8] = accL[mt][nt][3] + b1;
          s.xrT[n0  ][m0+8] = accR[mt][nt][2] + c0;
          s.xrT[n0+1][m0+8] = accR[mt][nt][3] + c1;
        }
      }
    __syncthreads();

    // ---- edge logits: att . leaky_relu(xl[src] + xr[dst]) ----
    for (int i = 0; i < 24; ++i) {          // 8 warps * 24 = 192 edges
      int eg = warp + 8*i;
      int g = eg >> 6, e = eg & 63;
      int gs = g*J + c_esrc[e];
      int gd = g*J + c_edst[e];
      float acc = 0.0f;
      #pragma unroll
      for (int q = 0; q < 4; ++q) {
        int cc = lane + 32*q;
        float v = s.xlT[cc][gs] + s.xrT[cc][gd];
        v = (v > 0.0f) ? v : 0.2f*v;
        acc += s.att[cc]*v;
      }
      #pragma unroll
      for (int o = 16; o > 0; o >>= 1)
        acc += __shfl_xor_sync(0xffffffffu, acc, o);
      if (lane == 0) s.logit[eg] = acc;
    }
    __syncthreads();

    // ---- segment softmax ----
    if (t < MROWS) {
      int g = t / J, n = t % J;
      const float* lg = &s.logit[g*NE];
      float m = -1e30f;
      #pragma unroll
      for (int e = 0; e < NE; ++e) if (EDST[e] == n) m = fmaxf(m, lg[e]);
      float d = 0.0f;
      #pragma unroll
      for (int e = 0; e < NE; ++e) if (EDST[e] == n) d += expf(lg[e] - m);
      s.mx[t] = m; s.den[t] = d;
    }
    __syncthreads();
    if (t < GPB*NE) {
      int g = t >> 6, e = t & 63;
      int dn = g*J + c_edst[e];
      s.aw[t] = expf(s.logit[t] - s.mx[dn]) / s.den[dn];
    }
    __syncthreads();

    // ---- aggregation + gate; layer<3 -> Ah/Al, layer3 -> out = x + h ----
    for (int it = 0; it < 2; ++it) {
      int idx = t + it*NTH;
      if (idx < GPB*C) {
        int g = idx >> 7, cc = idx & 127;
        float acc[J];
        #pragma unroll
        for (int n = 0; n < J; ++n) acc[n] = s.bias[cc];
        const float* ag = &s.aw[g*NE];
        #pragma unroll
        for (int e = 0; e < NE; ++e)
          acc[EDST[e]] += ag[e] * s.xlT[cc][g*J + ESRC[e]];
        #pragma unroll
        for (int n = 0; n < J; ++n) {
          int r = g*J + n;
          float v = acc[n];
          float xv = xblk[r*C + cc];
          if (layer > 0) v = oms*v + sg*xv;
          if (layer < 3) {
            ushort hi = bf16u(v);
            *reinterpret_cast<ushort*>(reinterpret_cast<char*>(s.Ah) + swzA(r, cc)) = hi;
            *reinterpret_cast<ushort*>(reinterpret_cast<char*>(s.Al) + swzA(r, cc)) =
                bf16u(v - __bfloat162float(__ushort_as_bfloat16(hi)));
          } else {
            out[(size_t)(node0 + r)*C + cc] = xv + v;
          }
        }
      }
    }
  }
}

extern "C" void kernel_launch(void* const* d_in, const int* in_sizes, int n_in,
                              void* d_out, int out_size)
{
  const float* x        = (const float*)d_in[0];
  const float* ln_gamma = (const float*)d_in[1];
  const float* ln_beta  = (const float*)d_in[2];
  const float* alpha    = (const float*)d_in[3];
  const float* Wl       = (const float*)d_in[4];
  const float* bl       = (const float*)d_in[5];
  const float* Wr       = (const float*)d_in[6];
  const float* br       = (const float*)d_in[7];
  const float* att      = (const float*)d_in[8];
  const float* bias     = (const float*)d_in[9];
  (void)in_sizes; (void)n_in; (void)out_size;

  int smem = (int)sizeof(Smem) + 1024;
  (void)cudaFuncSetAttribute(rgat_hmma_kernel,
                             cudaFuncAttributeMaxDynamicSharedMemorySize, smem);
  rgat_hmma_kernel<<<NBLOCKS, NTH, smem>>>(
      x, ln_gamma, ln_beta, alpha, Wl, bl, Wr, br, att, bias, (float*)d_out);
}

// round 7
// speedup vs baseline: 1.4217x; 1.2424x over previous
#include <cuda_runtime.h>
#include <cuda_bf16.h>
#include <math.h>
#include <stdint.h>

// RGAT: 4x GATv2 over 15552 independent 17-node graphs, C=128.
// Fused per-block (3 graphs); GEMM core = mma.sync m16n8k16 bf16, split hi/lo
// precision, fp32 accum. 512 threads/block (16 warps) for latency hiding.

namespace {
constexpr int J   = 17;
constexpr int C   = 128;
constexpr int GPB = 3;
constexpr int MROWS = GPB * J;           // 51
constexpr int MPAD  = 64;                // MMA M
constexpr int NE  = 64;
constexpr int NTH = 512;
constexpr int NGRAPHS = 15552;
constexpr int NBLOCKS = NGRAPHS / GPB;   // 5184
constexpr int MPADT = 53;                // xlT/xrT row stride (odd -> no conflicts)
}

__device__ constexpr int ESRC[NE] = {
  0,0,0,1,1,2,2,3,4,4,5,5,6,7,7,8,8,8,8,9,9,10,11,11,12,12,13,14,14,15,15,16,
  1,4,7,0,2,1,3,2,0,5,4,6,5,0,8,7,9,11,14,8,10,9,8,12,11,13,12,8,15,14,16,15
};
__device__ constexpr int EDST[NE] = {
  1,4,7,0,2,1,3,2,0,5,4,6,5,0,8,7,9,11,14,8,10,9,8,12,11,13,12,8,15,14,16,15,
  0,0,0,1,1,2,2,3,4,4,5,5,6,7,7,8,8,8,8,9,9,10,11,11,12,12,13,14,14,15,15,16
};
__device__ __constant__ int c_esrc[NE] = {
  0,0,0,1,1,2,2,3,4,4,5,5,6,7,7,8,8,8,8,9,9,10,11,11,12,12,13,14,14,15,15,16,
  1,4,7,0,2,1,3,2,0,5,4,6,5,0,8,7,9,11,14,8,10,9,8,12,11,13,12,8,15,14,16,15
};
__device__ __constant__ int c_edst[NE] = {
  1,4,7,0,2,1,3,2,0,5,4,6,5,0,8,7,9,11,14,8,10,9,8,12,11,13,12,8,15,14,16,15,
  0,0,0,1,1,2,2,3,4,4,5,5,6,7,7,8,8,8,8,9,9,10,11,11,12,12,13,14,14,15,15,16
};

struct Smem {
  __nv_bfloat16 Wlh[C*C];   // [k][n] swizzled, 32 KB each
  __nv_bfloat16 Wll[C*C];
  __nv_bfloat16 Wrh[C*C];
  __nv_bfloat16 Wrl[C*C];
  __nv_bfloat16 Ah[MPAD*C]; // [m][k] swizzled, 16 KB each
  __nv_bfloat16 Al[MPAD*C];
  float xlT[C][MPADT];      // 27136 B each
  float xrT[C][MPADT];
  float bl[C], br[C], att[C], bias[C];
  float logit[GPB*NE], aw[GPB*NE];
  float mx[MROWS], den[MROWS];
};

// ---------------- helpers ----------------
__device__ __forceinline__ uint32_t smem_u32(const void* p) {
  uint32_t a;
  asm("{ .reg .u64 t; cvta.to.shared.u64 t, %1; cvt.u32.u64 %0, t; }" : "=r"(a) : "l"(p));
  return a;
}
__device__ __forceinline__ void ldsm4(uint32_t* f, uint32_t a) {
  asm volatile("ldmatrix.sync.aligned.m8n8.x4.shared.b16 {%0,%1,%2,%3}, [%4];"
    : "=r"(f[0]),"=r"(f[1]),"=r"(f[2]),"=r"(f[3]) : "r"(a));
}
__device__ __forceinline__ void ldsm2t(uint32_t* f, uint32_t a) {
  asm volatile("ldmatrix.sync.aligned.m8n8.x2.trans.shared.b16 {%0,%1}, [%2];"
    : "=r"(f[0]),"=r"(f[1]) : "r"(a));
}
__device__ __forceinline__ void mma16816(float* d, const uint32_t* a, const uint32_t* b) {
  asm volatile("mma.sync.aligned.m16n8k16.row.col.f32.bf16.bf16.f32 "
    "{%0,%1,%2,%3}, {%4,%5,%6,%7}, {%8,%9}, {%0,%1,%2,%3};"
    : "+f"(d[0]),"+f"(d[1]),"+f"(d[2]),"+f"(d[3])
    : "r"(a[0]),"r"(a[1]),"r"(a[2]),"r"(a[3]), "r"(b[0]),"r"(b[1]));
}
// A tile byte offset: row m, col k. 256B rows, 16B chunks XOR-swizzled by m&7.
__device__ __forceinline__ uint32_t swzA(int m, int k) {
  return (uint32_t)(m*256 + ((((k>>3) ^ (m&7))<<4) | ((k&7)*2)));
}
__device__ __forceinline__ ushort bf16u(float v) {
  return __bfloat16_as_ushort(__float2bfloat16(v));
}

__global__ __launch_bounds__(NTH, 1)
void rgat_hmma_kernel(const float* __restrict__ x,
                      const float* __restrict__ ln_gamma,
                      const float* __restrict__ ln_beta,
                      const float* __restrict__ alpha,
                      const float* __restrict__ Wl,
                      const float* __restrict__ bl,
                      const float* __restrict__ Wr,
                      const float* __restrict__ br,
                      const float* __restrict__ att,
                      const float* __restrict__ bias,
                      float* __restrict__ out)
{
  extern __shared__ char raw[];
  uintptr_t pa = ((uintptr_t)raw + 1023) & ~(uintptr_t)1023;
  Smem& s = *reinterpret_cast<Smem*>(pa);

  const int t    = threadIdx.x;
  const int warp = t >> 5;
  const int lane = t & 31;
  const int node0 = blockIdx.x * MROWS;
  const float* xblk = x + (size_t)node0 * C;

  // ---- prologue: zero A tiles, W tiles hi/lo swizzled, vectors ----
  for (int i = t; i < MPAD*C/2; i += NTH) {
    reinterpret_cast<uint32_t*>(s.Ah)[i] = 0u;
    reinterpret_cast<uint32_t*>(s.Al)[i] = 0u;
  }
  for (int i = t; i < C*C/4; i += NTH) {
    int k = i >> 5, n4 = (i & 31) * 4;
    float4 vl = reinterpret_cast<const float4*>(Wl)[i];
    float4 vr = reinterpret_cast<const float4*>(Wr)[i];
    uint32_t off = (uint32_t)(k*256 + ((((n4>>3) ^ (k&7))<<4) | ((n4&7)*2)));
    ushort h0 = bf16u(vl.x), h1 = bf16u(vl.y), h2 = bf16u(vl.z), h3 = bf16u(vl.w);
    uint2 hp = make_uint2((uint32_t)h0 | ((uint32_t)h1 << 16),
                          (uint32_t)h2 | ((uint32_t)h3 << 16));
    uint2 lp = make_uint2(
      (uint32_t)bf16u(vl.x - __bfloat162float(__ushort_as_bfloat16(h0))) |
      ((uint32_t)bf16u(vl.y - __bfloat162float(__ushort_as_bfloat16(h1))) << 16),
      (uint32_t)bf16u(vl.z - __bfloat162float(__ushort_as_bfloat16(h2))) |
      ((uint32_t)bf16u(vl.w - __bfloat162float(__ushort_as_bfloat16(h3))) << 16));
    *reinterpret_cast<uint2*>(reinterpret_cast<char*>(s.Wlh) + off) = hp;
    *reinterpret_cast<uint2*>(reinterpret_cast<char*>(s.Wll) + off) = lp;
    h0 = bf16u(vr.x); h1 = bf16u(vr.y); h2 = bf16u(vr.z); h3 = bf16u(vr.w);
    hp = make_uint2((uint32_t)h0 | ((uint32_t)h1 << 16),
                    (uint32_t)h2 | ((uint32_t)h3 << 16));
    lp = make_uint2(
      (uint32_t)bf16u(vr.x - __bfloat162float(__ushort_as_bfloat16(h0))) |
      ((uint32_t)bf16u(vr.y - __bfloat162float(__ushort_as_bfloat16(h1))) << 16),
      (uint32_t)bf16u(vr.z - __bfloat162float(__ushort_as_bfloat16(h2))) |
      ((uint32_t)bf16u(vr.w - __bfloat162float(__ushort_as_bfloat16(h3))) << 16));
    *reinterpret_cast<uint2*>(reinterpret_cast<char*>(s.Wrh) + off) = hp;
    *reinterpret_cast<uint2*>(reinterpret_cast<char*>(s.Wrl) + off) = lp;
  }
  for (int i = t; i < C; i += NTH) {
    s.bl[i] = bl[i]; s.br[i] = br[i]; s.att[i] = att[i]; s.bias[i] = bias[i];
  }
  const float sg  = 1.0f / (1.0f + __expf(-alpha[0]));
  const float oms = 1.0f - sg;

  // ---- LayerNorm -> Ah/Al (hi/lo bf16) ----
  for (int r = warp; r < MROWS; r += 16) {
    float v0 = xblk[r*C + lane],      v1 = xblk[r*C + lane + 32];
    float v2 = xblk[r*C + lane + 64], v3 = xblk[r*C + lane + 96];
    float sum = v0+v1+v2+v3, sq = v0*v0+v1*v1+v2*v2+v3*v3;
    #pragma unroll
    for (int o = 16; o > 0; o >>= 1) {
      sum += __shfl_xor_sync(0xffffffffu, sum, o);
      sq  += __shfl_xor_sync(0xffffffffu, sq,  o);
    }
    float mu = sum * (1.0f/C);
    float inv = rsqrtf(sq * (1.0f/C) - mu*mu + 1e-5f);
    #pragma unroll
    for (int q = 0; q < 4; ++q) {
      int cc = lane + 32*q;
      float vv = (q==0?v0:q==1?v1:q==2?v2:v3);
      float hval = (vv-mu)*inv*ln_gamma[cc] + ln_beta[cc];
      ushort hi = bf16u(hval);
      *reinterpret_cast<ushort*>(reinterpret_cast<char*>(s.Ah) + swzA(r, cc)) = hi;
      *reinterpret_cast<ushort*>(reinterpret_cast<char*>(s.Al) + swzA(r, cc)) =
          bf16u(hval - __bfloat162float(__ushort_as_bfloat16(hi)));
    }
  }

  const uint32_t aAh  = smem_u32(s.Ah),  aAl  = smem_u32(s.Al);
  const uint32_t aWlh = smem_u32(s.Wlh), aWll = smem_u32(s.Wll);
  const uint32_t aWrh = smem_u32(s.Wrh), aWrl = smem_u32(s.Wrl);
  // lane decomposition for ldmatrix addressing
  const int rA = lane & 7;
  const int rowOffA = ((lane>>3)&1)*8 + rA;   // matrix row offset within m16
  const int chOffA  = (lane>>4);              // k-chunk offset (0/1)
  const int rB  = lane & 7;
  const int miB = (lane>>3)&1;
  // this warp's 8 output columns
  const int n0w = warp * 8;
  // epilogue lane mapping
  const int eM = lane >> 2;
  const int eN = 2*(lane & 3);

  #pragma unroll 1
  for (int layer = 0; layer < 4; ++layer) {
    __syncthreads();   // Ah/Al ready (LN or previous aggregation)

    float accL[4][4];
    float accR[4][4];
    #pragma unroll
    for (int mt = 0; mt < 4; ++mt)
      #pragma unroll
      for (int q = 0; q < 4; ++q) { accL[mt][q] = 0.f; accR[mt][q] = 0.f; }

    #pragma unroll
    for (int ks = 0; ks < 8; ++ks) {
      uint32_t fAh[4][4], fAl[4][4];
      #pragma unroll
      for (int mt = 0; mt < 4; ++mt) {
        uint32_t ar = (uint32_t)((mt*16 + rowOffA)*256 + (((2*ks + chOffA) ^ rA)<<4));
        ldsm4(fAh[mt], aAh + ar);
        ldsm4(fAl[mt], aAl + ar);
      }
      uint32_t boff = (uint32_t)((ks*16 + miB*8 + rB)*256 + (((n0w>>3) ^ rB)<<4));
      uint32_t bh[2], blo[2];
      ldsm2t(bh,  aWlh + boff);
      ldsm2t(blo, aWll + boff);
      #pragma unroll
      for (int mt = 0; mt < 4; ++mt) {
        mma16816(accL[mt], fAh[mt], bh);
        mma16816(accL[mt], fAl[mt], bh);
        mma16816(accL[mt], fAh[mt], blo);
      }
      ldsm2t(bh,  aWrh + boff);
      ldsm2t(blo, aWrl + boff);
      #pragma unroll
      for (int mt = 0; mt < 4; ++mt) {
        mma16816(accR[mt], fAh[mt], bh);
        mma16816(accR[mt], fAl[mt], bh);
        mma16816(accR[mt], fAh[mt], blo);
      }
    }

    // ---- epilogue: fragments -> xlT/xrT (+bias) ----
    {
      int n0 = n0w + eN;
      float b0 = s.bl[n0], b1 = s.bl[n0+1];
      float c0 = s.br[n0], c1 = s.br[n0+1];
      #pragma unroll
      for (int mt = 0; mt < 4; ++mt) {
        int m0 = mt*16 + eM;
        if (m0 < MROWS) {
          s.xlT[n0  ][m0] = accL[mt][0] + b0;
          s.xlT[n0+1][m0] = accL[mt][1] + b1;
          s.xrT[n0  ][m0] = accR[mt][0] + c0;
          s.xrT[n0+1][m0] = accR[mt][1] + c1;
        }
        if (m0+8 < MROWS) {
          s.xlT[n0  ][m0+8] = accL[mt][2] + b0;
          s.xlT[n0+1][m0+8] = accL[mt][3] + b1;
          s.xrT[n0  ][m0+8] = accR[mt][2] + c0;
          s.xrT[n0+1][m0+8] = accR[mt][3] + c1;
        }
      }
    }
    __syncthreads();

    // ---- edge logits: att . leaky_relu(xl[src] + xr[dst]) ----
    #pragma unroll
    for (int i = 0; i < 12; ++i) {          // 16 warps * 12 = 192 edges
      int eg = warp + 16*i;
      int g = eg >> 6, e = eg & 63;
      int gs = g*J + c_esrc[e];
      int gd = g*J + c_edst[e];
      float acc = 0.0f;
      #pragma unroll
      for (int q = 0; q < 4; ++q) {
        int cc = lane + 32*q;
        float v = s.xlT[cc][gs] + s.xrT[cc][gd];
        v = (v > 0.0f) ? v : 0.2f*v;
        acc += s.att[cc]*v;
      }
      #pragma unroll
      for (int o = 16; o > 0; o >>= 1)
        acc += __shfl_xor_sync(0xffffffffu, acc, o);
      if (lane == 0) s.logit[eg] = acc;
    }
    __syncthreads();

    // ---- segment softmax ----
    if (t < MROWS) {
      int g = t / J, n = t % J;
      const float* lg = &s.logit[g*NE];
      float m = -1e30f;
      #pragma unroll
      for (int e = 0; e < NE; ++e) if (EDST[e] == n) m = fmaxf(m, lg[e]);
      float d = 0.0f;
      #pragma unroll
      for (int e = 0; e < NE; ++e) if (EDST[e] == n) d += __expf(lg[e] - m);
      s.mx[t] = m; s.den[t] = d;
    }
    __syncthreads();
    if (t < GPB*NE) {
      int g = t >> 6, e = t & 63;
      int dn = g*J + c_edst[e];
      s.aw[t] = __expf(s.logit[t] - s.mx[dn]) / s.den[dn];
    }
    __syncthreads();

    // ---- aggregation + gate; layer<3 -> Ah/Al, layer3 -> out = x + h ----
    if (t < GPB*C) {
      int g = t >> 7, cc = t & 127;
      float acc[J];
      #pragma unroll
      for (int n = 0; n < J; ++n) acc[n] = s.bias[cc];
      const float* ag = &s.aw[g*NE];
      #pragma unroll
      for (int e = 0; e < NE; ++e)
        acc[EDST[e]] += ag[e] * s.xlT[cc][g*J + ESRC[e]];
      #pragma unroll
      for (int n = 0; n < J; ++n) {
        int r = g*J + n;
        float v = acc[n];
        float xv = xblk[r*C + cc];
        if (layer > 0) v = oms*v + sg*xv;
        if (layer < 3) {
          ushort hi = bf16u(v);
          *reinterpret_cast<ushort*>(reinterpret_cast<char*>(s.Ah) + swzA(r, cc)) = hi;
          *reinterpret_cast<ushort*>(reinterpret_cast<char*>(s.Al) + swzA(r, cc)) =
              bf16u(v - __bfloat162float(__ushort_as_bfloat16(hi)));
        } else {
          out[(size_t)(node0 + r)*C + cc] = xv + v;
        }
      }
    }
  }
}

extern "C" void kernel_launch(void* const* d_in, const int* in_sizes, int n_in,
                              void* d_out, int out_size)
{
  const float* x        = (const float*)d_in[0];
  const float* ln_gamma = (const float*)d_in[1];
  const float* ln_beta  = (const float*)d_in[2];
  const float* alpha    = (const float*)d_in[3];
  const float* Wl       = (const float*)d_in[4];
  const float* bl       = (const float*)d_in[5];
  const float* Wr       = (const float*)d_in[6];
  const float* br       = (const float*)d_in[7];
  const float* att      = (const float*)d_in[8];
  const float* bias     = (const float*)d_in[9];
  (void)in_sizes; (void)n_in; (void)out_size;

  int smem = (int)sizeof(Smem) + 1024;
  (void)cudaFuncSetAttribute(rgat_hmma_kernel,
                             cudaFuncAttributeMaxDynamicSharedMemorySize, smem);
  rgat_hmma_kernel<<<NBLOCKS, NTH, smem>>>(
      x, ln_gamma, ln_beta, alpha, Wl, bl, Wr, br, att, bias, (float*)d_out);
}

// round 8
// speedup vs baseline: 1.4225x; 1.0006x over previous
#include <cuda_runtime.h>
#include <cuda_bf16.h>
#include <math.h>
#include <stdint.h>

// RGAT: 4x GATv2 over 15552 independent 17-node graphs, C=128.
// Fused per-block (3 graphs); GEMM core = mma.sync m16n8k16 bf16, split hi/lo
// precision, fp32 accum. 512 threads/block (16 warps) for latency hiding.

namespace {
constexpr int J   = 17;
constexpr int C   = 128;
constexpr int GPB = 3;
constexpr int MROWS = GPB * J;           // 51
constexpr int MPAD  = 64;                // MMA M
constexpr int NE  = 64;
constexpr int NTH = 512;
constexpr int NGRAPHS = 15552;
constexpr int NBLOCKS = NGRAPHS / GPB;   // 5184
constexpr int MPADT = 53;                // xlT/xrT row stride (odd -> no conflicts)
}

__device__ constexpr int ESRC[NE] = {
  0,0,0,1,1,2,2,3,4,4,5,5,6,7,7,8,8,8,8,9,9,10,11,11,12,12,13,14,14,15,15,16,
  1,4,7,0,2,1,3,2,0,5,4,6,5,0,8,7,9,11,14,8,10,9,8,12,11,13,12,8,15,14,16,15
};
__device__ constexpr int EDST[NE] = {
  1,4,7,0,2,1,3,2,0,5,4,6,5,0,8,7,9,11,14,8,10,9,8,12,11,13,12,8,15,14,16,15,
  0,0,0,1,1,2,2,3,4,4,5,5,6,7,7,8,8,8,8,9,9,10,11,11,12,12,13,14,14,15,15,16
};
__device__ __constant__ int c_esrc[NE] = {
  0,0,0,1,1,2,2,3,4,4,5,5,6,7,7,8,8,8,8,9,9,10,11,11,12,12,13,14,14,15,15,16,
  1,4,7,0,2,1,3,2,0,5,4,6,5,0,8,7,9,11,14,8,10,9,8,12,11,13,12,8,15,14,16,15
};
__device__ __constant__ int c_edst[NE] = {
  1,4,7,0,2,1,3,2,0,5,4,6,5,0,8,7,9,11,14,8,10,9,8,12,11,13,12,8,15,14,16,15,
  0,0,0,1,1,2,2,3,4,4,5,5,6,7,7,8,8,8,8,9,9,10,11,11,12,12,13,14,14,15,15,16
};

struct Smem {
  __nv_bfloat16 Wlh[C*C];   // [k][n] swizzled, 32 KB each
  __nv_bfloat16 Wll[C*C];
  __nv_bfloat16 Wrh[C*C];
  __nv_bfloat16 Wrl[C*C];
  __nv_bfloat16 Ah[MPAD*C]; // [m][k] swizzled, 16 KB each
  __nv_bfloat16 Al[MPAD*C];
  float xlT[C][MPADT];      // 27136 B each
  float xrT[C][MPADT];
  float bl[C], br[C], att[C], bias[C];
  float logit[GPB*NE], aw[GPB*NE];
  float mx[MROWS], den[MROWS];
};

// ---------------- helpers ----------------
__device__ __forceinline__ uint32_t smem_u32(const void* p) {
  uint32_t a;
  asm("{ .reg .u64 t; cvta.to.shared.u64 t, %1; cvt.u32.u64 %0, t; }" : "=r"(a) : "l"(p));
  return a;
}
__device__ __forceinline__ void ldsm4(uint32_t* f, uint32_t a) {
  asm volatile("ldmatrix.sync.aligned.m8n8.x4.shared.b16 {%0,%1,%2,%3}, [%4];"
    : "=r"(f[0]),"=r"(f[1]),"=r"(f[2]),"=r"(f[3]) : "r"(a));
}
__device__ __forceinline__ void ldsm2t(uint32_t* f, uint32_t a) {
  asm volatile("ldmatrix.sync.aligned.m8n8.x2.trans.shared.b16 {%0,%1}, [%2];"
    : "=r"(f[0]),"=r"(f[1]) : "r"(a));
}
__device__ __forceinline__ void mma16816(float* d, const uint32_t* a, const uint32_t* b) {
  asm volatile("mma.sync.aligned.m16n8k16.row.col.f32.bf16.bf16.f32 "
    "{%0,%1,%2,%3}, {%4,%5,%6,%7}, {%8,%9}, {%0,%1,%2,%3};"
    : "+f"(d[0]),"+f"(d[1]),"+f"(d[2]),"+f"(d[3])
    : "r"(a[0]),"r"(a[1]),"r"(a[2]),"r"(a[3]), "r"(b[0]),"r"(b[1]));
}
// A tile byte offset: row m, col k. 256B rows, 16B chunks XOR-swizzled by m&7.
__device__ __forceinline__ uint32_t swzA(int m, int k) {
  return (uint32_t)(m*256 + ((((k>>3) ^ (m&7))<<4) | ((k&7)*2)));
}
__device__ __forceinline__ ushort bf16u(float v) {
  return __bfloat16_as_ushort(__float2bfloat16(v));
}

__global__ __launch_bounds__(NTH, 1)
void rgat_hmma_kernel(const float* __restrict__ x,
                      const float* __restrict__ ln_gamma,
                      const float* __restrict__ ln_beta,
                      const float* __restrict__ alpha,
                      const float* __restrict__ Wl,
                      const float* __restrict__ bl,
                      const float* __restrict__ Wr,
                      const float* __restrict__ br,
                      const float* __restrict__ att,
                      const float* __restrict__ bias,
                      float* __restrict__ out)
{
  extern __shared__ char raw[];
  uintptr_t pa = ((uintptr_t)raw + 1023) & ~(uintptr_t)1023;
  Smem& s = *reinterpret_cast<Smem*>(pa);

  const int t    = threadIdx.x;
  const int warp = t >> 5;
  const int lane = t & 31;
  const int node0 = blockIdx.x * MROWS;
  const float* xblk = x + (size_t)node0 * C;

  // ---- prologue: zero A tiles, W tiles hi/lo swizzled, vectors ----
  for (int i = t; i < MPAD*C/2; i += NTH) {
    reinterpret_cast<uint32_t*>(s.Ah)[i] = 0u;
    reinterpret_cast<uint32_t*>(s.Al)[i] = 0u;
  }
  for (int i = t; i < C*C/4; i += NTH) {
    int k = i >> 5, n4 = (i & 31) * 4;
    float4 vl = reinterpret_cast<const float4*>(Wl)[i];
    float4 vr = reinterpret_cast<const float4*>(Wr)[i];
    uint32_t off = (uint32_t)(k*256 + ((((n4>>3) ^ (k&7))<<4) | ((n4&7)*2)));
    ushort h0 = bf16u(vl.x), h1 = bf16u(vl.y), h2 = bf16u(vl.z), h3 = bf16u(vl.w);
    uint2 hp = make_uint2((uint32_t)h0 | ((uint32_t)h1 << 16),
                          (uint32_t)h2 | ((uint32_t)h3 << 16));
    uint2 lp = make_uint2(
      (uint32_t)bf16u(vl.x - __bfloat162float(__ushort_as_bfloat16(h0))) |
      ((uint32_t)bf16u(vl.y - __bfloat162float(__ushort_as_bfloat16(h1))) << 16),
      (uint32_t)bf16u(vl.z - __bfloat162float(__ushort_as_bfloat16(h2))) |
      ((uint32_t)bf16u(vl.w - __bfloat162float(__ushort_as_bfloat16(h3))) << 16));
    *reinterpret_cast<uint2*>(reinterpret_cast<char*>(s.Wlh) + off) = hp;
    *reinterpret_cast<uint2*>(reinterpret_cast<char*>(s.Wll) + off) = lp;
    h0 = bf16u(vr.x); h1 = bf16u(vr.y); h2 = bf16u(vr.z); h3 = bf16u(vr.w);
    hp = make_uint2((uint32_t)h0 | ((uint32_t)h1 << 16),
                    (uint32_t)h2 | ((uint32_t)h3 << 16));
    lp = make_uint2(
      (uint32_t)bf16u(vr.x - __bfloat162float(__ushort_as_bfloat16(h0))) |
      ((uint32_t)bf16u(vr.y - __bfloat162float(__ushort_as_bfloat16(h1))) << 16),
      (uint32_t)bf16u(vr.z - __bfloat162float(__ushort_as_bfloat16(h2))) |
      ((uint32_t)bf16u(vr.w - __bfloat162float(__ushort_as_bfloat16(h3))) << 16));
    *reinterpret_cast<uint2*>(reinterpret_cast<char*>(s.Wrh) + off) = hp;
    *reinterpret_cast<uint2*>(reinterpret_cast<char*>(s.Wrl) + off) = lp;
  }
  for (int i = t; i < C; i += NTH) {
    s.bl[i] = bl[i]; s.br[i] = br[i]; s.att[i] = att[i]; s.bias[i] = bias[i];
  }
  const float sg  = 1.0f / (1.0f + __expf(-alpha[0]));
  const float oms = 1.0f - sg;

  // ---- LayerNorm -> Ah/Al (hi/lo bf16) ----
  for (int r = warp; r < MROWS; r += 16) {
    float v0 = xblk[r*C + lane],      v1 = xblk[r*C + lane + 32];
    float v2 = xblk[r*C + lane + 64], v3 = xblk[r*C + lane + 96];
    float sum = v0+v1+v2+v3, sq = v0*v0+v1*v1+v2*v2+v3*v3;
    #pragma unroll
    for (int o = 16; o > 0; o >>= 1) {
      sum += __shfl_xor_sync(0xffffffffu, sum, o);
      sq  += __shfl_xor_sync(0xffffffffu, sq,  o);
    }
    float mu = sum * (1.0f/C);
    float inv = rsqrtf(sq * (1.0f/C) - mu*mu + 1e-5f);
    #pragma unroll
    for (int q = 0; q < 4; ++q) {
      int cc = lane + 32*q;
      float vv = (q==0?v0:q==1?v1:q==2?v2:v3);
      float hval = (vv-mu)*inv*ln_gamma[cc] + ln_beta[cc];
      ushort hi = bf16u(hval);
      *reinterpret_cast<ushort*>(reinterpret_cast<char*>(s.Ah) + swzA(r, cc)) = hi;
      *reinterpret_cast<ushort*>(reinterpret_cast<char*>(s.Al) + swzA(r, cc)) =
          bf16u(hval - __bfloat162float(__ushort_as_bfloat16(hi)));
    }
  }

  const uint32_t aAh  = smem_u32(s.Ah),  aAl  = smem_u32(s.Al);
  const uint32_t aWlh = smem_u32(s.Wlh), aWll = smem_u32(s.Wll);
  const uint32_t aWrh = smem_u32(s.Wrh), aWrl = smem_u32(s.Wrl);
  // lane decomposition for ldmatrix addressing
  const int rA = lane & 7;
  const int rowOffA = ((lane>>3)&1)*8 + rA;   // matrix row offset within m16
  const int chOffA  = (lane>>4);              // k-chunk offset (0/1)
  const int rB  = lane & 7;
  const int miB = (lane>>3)&1;
  // this warp's 8 output columns
  const int n0w = warp * 8;
  // epilogue lane mapping
  const int eM = lane >> 2;
  const int eN = 2*(lane & 3);

  #pragma unroll 1
  for (int layer = 0; layer < 4; ++layer) {
    __syncthreads();   // Ah/Al ready (LN or previous aggregation)

    float accL[4][4];
    float accR[4][4];
    #pragma unroll
    for (int mt = 0; mt < 4; ++mt)
      #pragma unroll
      for (int q = 0; q < 4; ++q) { accL[mt][q] = 0.f; accR[mt][q] = 0.f; }

    #pragma unroll
    for (int ks = 0; ks < 8; ++ks) {
      uint32_t fAh[4][4], fAl[4][4];
      #pragma unroll
      for (int mt = 0; mt < 4; ++mt) {
        uint32_t ar = (uint32_t)((mt*16 + rowOffA)*256 + (((2*ks + chOffA) ^ rA)<<4));
        ldsm4(fAh[mt], aAh + ar);
        ldsm4(fAl[mt], aAl + ar);
      }
      uint32_t boff = (uint32_t)((ks*16 + miB*8 + rB)*256 + (((n0w>>3) ^ rB)<<4));
      uint32_t bh[2], blo[2];
      ldsm2t(bh,  aWlh + boff);
      ldsm2t(blo, aWll + boff);
      #pragma unroll
      for (int mt = 0; mt < 4; ++mt) {
        mma16816(accL[mt], fAh[mt], bh);
        mma16816(accL[mt], fAl[mt], bh);
        mma16816(accL[mt], fAh[mt], blo);
      }
      ldsm2t(bh,  aWrh + boff);
      ldsm2t(blo, aWrl + boff);
      #pragma unroll
      for (int mt = 0; mt < 4; ++mt) {
        mma16816(accR[mt], fAh[mt], bh);
        mma16816(accR[mt], fAl[mt], bh);
        mma16816(accR[mt], fAh[mt], blo);
      }
    }

    // ---- epilogue: fragments -> xlT/xrT (+bias) ----
    {
      int n0 = n0w + eN;
      float b0 = s.bl[n0], b1 = s.bl[n0+1];
      float c0 = s.br[n0], c1 = s.br[n0+1];
      #pragma unroll
      for (int mt = 0; mt < 4; ++mt) {
        int m0 = mt*16 + eM;
        if (m0 < MROWS) {
          s.xlT[n0  ][m0] = accL[mt][0] + b0;
          s.xlT[n0+1][m0] = accL[mt][1] + b1;
          s.xrT[n0  ][m0] = accR[mt][0] + c0;
          s.xrT[n0+1][m0] = accR[mt][1] + c1;
        }
        if (m0+8 < MROWS) {
          s.xlT[n0  ][m0+8] = accL[mt][2] + b0;
          s.xlT[n0+1][m0+8] = accL[mt][3] + b1;
          s.xrT[n0  ][m0+8] = accR[mt][2] + c0;
          s.xrT[n0+1][m0+8] = accR[mt][3] + c1;
        }
      }
    }
    __syncthreads();

    // ---- edge logits: att . leaky_relu(xl[src] + xr[dst]) ----
    #pragma unroll
    for (int i = 0; i < 12; ++i) {          // 16 warps * 12 = 192 edges
      int eg = warp + 16*i;
      int g = eg >> 6, e = eg & 63;
      int gs = g*J + c_esrc[e];
      int gd = g*J + c_edst[e];
      float acc = 0.0f;
      #pragma unroll
      for (int q = 0; q < 4; ++q) {
        int cc = lane + 32*q;
        float v = s.xlT[cc][gs] + s.xrT[cc][gd];
        v = (v > 0.0f) ? v : 0.2f*v;
        acc += s.att[cc]*v;
      }
      #pragma unroll
      for (int o = 16; o > 0; o >>= 1)
        acc += __shfl_xor_sync(0xffffffffu, acc, o);
      if (lane == 0) s.logit[eg] = acc;
    }
    __syncthreads();

    // ---- segment softmax ----
    if (t < MROWS) {
      int g = t / J, n = t % J;
      const float* lg = &s.logit[g*NE];
      float m = -1e30f;
      #pragma unroll
      for (int e = 0; e < NE; ++e) if (EDST[e] == n) m = fmaxf(m, lg[e]);
      float d = 0.0f;
      #pragma unroll
      for (int e = 0; e < NE; ++e) if (EDST[e] == n) d += __expf(lg[e] - m);
      s.mx[t] = m; s.den[t] = d;
    }
    __syncthreads();
    if (t < GPB*NE) {
      int g = t >> 6, e = t & 63;
      int dn = g*J + c_edst[e];
      s.aw[t] = __expf(s.logit[t] - s.mx[dn]) / s.den[dn];
    }
    __syncthreads();

    // ---- aggregation + gate; layer<3 -> Ah/Al, layer3 -> out = x + h ----
    if (t < GPB*C) {
      int g = t >> 7, cc = t & 127;
      float acc[J];
      #pragma unroll
      for (int n = 0; n < J; ++n) acc[n] = s.bias[cc];
      const float* ag = &s.aw[g*NE];
      #pragma unroll
      for (int e = 0; e < NE; ++e)
        acc[EDST[e]] += ag[e] * s.xlT[cc][g*J + ESRC[e]];
      #pragma unroll
      for (int n = 0; n < J; ++n) {
        int r = g*J + n;
        float v = acc[n];
        float xv = xblk[r*C + cc];
        if (layer > 0) v = oms*v + sg*xv;
        if (layer < 3) {
          ushort hi = bf16u(v);
          *reinterpret_cast<ushort*>(reinterpret_cast<char*>(s.Ah) + swzA(r, cc)) = hi;
          *reinterpret_cast<ushort*>(reinterpret_cast<char*>(s.Al) + swzA(r, cc)) =
              bf16u(v - __bfloat162float(__ushort_as_bfloat16(hi)));
        } else {
          out[(size_t)(node0 + r)*C + cc] = xv + v;
        }
      }
    }
  }
}

extern "C" void kernel_launch(void* const* d_in, const int* in_sizes, int n_in,
                              void* d_out, int out_size)
{
  const float* x        = (const float*)d_in[0];
  const float* ln_gamma = (const float*)d_in[1];
  const float* ln_beta  = (const float*)d_in[2];
  const float* alpha    = (const float*)d_in[3];
  const float* Wl       = (const float*)d_in[4];
  const float* bl       = (const float*)d_in[5];
  const float* Wr       = (const float*)d_in[6];
  const float* br       = (const float*)d_in[7];
  const float* att      = (const float*)d_in[8];
  const float* bias     = (const float*)d_in[9];
  (void)in_sizes; (void)n_in; (void)out_size;

  int smem = (int)sizeof(Smem) + 1024;
  (void)cudaFuncSetAttribute(rgat_hmma_kernel,
                             cudaFuncAttributeMaxDynamicSharedMemorySize, smem);
  rgat_hmma_kernel<<<NBLOCKS, NTH, smem>>>(
      x, ln_gamma, ln_beta, alpha, Wl, bl, Wr, br, att, bias, (float*)d_out);
}

// round 9
// speedup vs baseline: 1.5948x; 1.1212x over previous
#include <cuda_runtime.h>
#include <cuda_bf16.h>
#include <math.h>
#include <stdint.h>

// RGAT: 4x GATv2 over 15552 independent 17-node graphs, C=128.
// Fused per-block (4 graphs); mma.sync m16n8k16 bf16 split hi/lo, fp32 accum.
// xrT aliases the A-tile region (never live simultaneously) to fit GPB=4.

namespace {
constexpr int J   = 17;
constexpr int C   = 128;
constexpr int GPB = 4;
constexpr int MROWS = GPB * J;           // 68
constexpr int MPAD  = 80;                // MMA M (5 m-tiles)
constexpr int NMT = MPAD / 16;           // 5
constexpr int NE  = 64;
constexpr int NTH = 512;
constexpr int NGRAPHS = 15552;
constexpr int NBLOCKS = NGRAPHS / GPB;   // 3888
constexpr int MPADT = 69;                // xlT/xrT row stride (odd)
constexpr int AUNION = 48 * 1024;        // union: Ah(20480)+Al(20480) | xrT(35328)
}

__device__ constexpr int ESRC[NE] = {
  0,0,0,1,1,2,2,3,4,4,5,5,6,7,7,8,8,8,8,9,9,10,11,11,12,12,13,14,14,15,15,16,
  1,4,7,0,2,1,3,2,0,5,4,6,5,0,8,7,9,11,14,8,10,9,8,12,11,13,12,8,15,14,16,15
};
__device__ constexpr int EDST[NE] = {
  1,4,7,0,2,1,3,2,0,5,4,6,5,0,8,7,9,11,14,8,10,9,8,12,11,13,12,8,15,14,16,15,
  0,0,0,1,1,2,2,3,4,4,5,5,6,7,7,8,8,8,8,9,9,10,11,11,12,12,13,14,14,15,15,16
};
__device__ __constant__ int c_esrc[NE] = {
  0,0,0,1,1,2,2,3,4,4,5,5,6,7,7,8,8,8,8,9,9,10,11,11,12,12,13,14,14,15,15,16,
  1,4,7,0,2,1,3,2,0,5,4,6,5,0,8,7,9,11,14,8,10,9,8,12,11,13,12,8,15,14,16,15
};
__device__ __constant__ int c_edst[NE] = {
  1,4,7,0,2,1,3,2,0,5,4,6,5,0,8,7,9,11,14,8,10,9,8,12,11,13,12,8,15,14,16,15,
  0,0,0,1,1,2,2,3,4,4,5,5,6,7,7,8,8,8,8,9,9,10,11,11,12,12,13,14,14,15,15,16
};

struct Smem {
  __nv_bfloat16 Wlh[C*C];   // [k][n] swizzled, 32 KB each
  __nv_bfloat16 Wll[C*C];
  __nv_bfloat16 Wrh[C*C];
  __nv_bfloat16 Wrl[C*C];
  char uni[AUNION];         // Ah @ +0 (20480), Al @ +20480  |  xrT @ +0 (35328)
  float xlT[C][MPADT];      // 35328
  float bl[C], br[C], att[C], bias[C];
  float logit[GPB*NE], aw[GPB*NE];
  float mx[MROWS], den[MROWS];
};

// ---------------- helpers ----------------
__device__ __forceinline__ uint32_t smem_u32(const void* p) {
  uint32_t a;
  asm("{ .reg .u64 t; cvta.to.shared.u64 t, %1; cvt.u32.u64 %0, t; }" : "=r"(a) : "l"(p));
  return a;
}
__device__ __forceinline__ void ldsm4(uint32_t* f, uint32_t a) {
  asm volatile("ldmatrix.sync.aligned.m8n8.x4.shared.b16 {%0,%1,%2,%3}, [%4];"
    : "=r"(f[0]),"=r"(f[1]),"=r"(f[2]),"=r"(f[3]) : "r"(a));
}
__device__ __forceinline__ void ldsm2t(uint32_t* f, uint32_t a) {
  asm volatile("ldmatrix.sync.aligned.m8n8.x2.trans.shared.b16 {%0,%1}, [%2];"
    : "=r"(f[0]),"=r"(f[1]) : "r"(a));
}
__device__ __forceinline__ void mma16816(float* d, const uint32_t* a, const uint32_t* b) {
  asm volatile("mma.sync.aligned.m16n8k16.row.col.f32.bf16.bf16.f32 "
    "{%0,%1,%2,%3}, {%4,%5,%6,%7}, {%8,%9}, {%0,%1,%2,%3};"
    : "+f"(d[0]),"+f"(d[1]),"+f"(d[2]),"+f"(d[3])
    : "r"(a[0]),"r"(a[1]),"r"(a[2]),"r"(a[3]), "r"(b[0]),"r"(b[1]));
}
// A tile byte offset: row m, col k. 256B rows, 16B chunks XOR-swizzled by m&7.
__device__ __forceinline__ uint32_t swzA(int m, int k) {
  return (uint32_t)(m*256 + ((((k>>3) ^ (m&7))<<4) | ((k&7)*2)));
}
__device__ __forceinline__ ushort bf16u(float v) {
  return __bfloat16_as_ushort(__float2bfloat16(v));
}

__global__ __launch_bounds__(NTH, 1)
void rgat_hmma_kernel(const float* __restrict__ x,
                      const float* __restrict__ ln_gamma,
                      const float* __restrict__ ln_beta,
                      const float* __restrict__ alpha,
                      const float* __restrict__ Wl,
                      const float* __restrict__ bl,
                      const float* __restrict__ Wr,
                      const float* __restrict__ br,
                      const float* __restrict__ att,
                      const float* __restrict__ bias,
                      float* __restrict__ out)
{
  extern __shared__ char raw[];
  uintptr_t pa = ((uintptr_t)raw + 1023) & ~(uintptr_t)1023;
  Smem& s = *reinterpret_cast<Smem*>(pa);

  char* Ah_base = s.uni;
  char* Al_base = s.uni + MPAD*C*2;                    // +20480
  float (*xrT)[MPADT] = reinterpret_cast<float (*)[MPADT]>(s.uni);

  const int t    = threadIdx.x;
  const int warp = t >> 5;
  const int lane = t & 31;
  const int node0 = blockIdx.x * MROWS;
  const float* xblk = x + (size_t)node0 * C;

  // ---- prologue: zero A union, W tiles hi/lo swizzled, vectors ----
  for (int i = t; i < AUNION/4; i += NTH)
    reinterpret_cast<uint32_t*>(s.uni)[i] = 0u;
  for (int i = t; i < C*C/4; i += NTH) {
    int k = i >> 5, n4 = (i & 31) * 4;
    float4 vl = reinterpret_cast<const float4*>(Wl)[i];
    float4 vr = reinterpret_cast<const float4*>(Wr)[i];
    uint32_t off = (uint32_t)(k*256 + ((((n4>>3) ^ (k&7))<<4) | ((n4&7)*2)));
    ushort h0 = bf16u(vl.x), h1 = bf16u(vl.y), h2 = bf16u(vl.z), h3 = bf16u(vl.w);
    uint2 hp = make_uint2((uint32_t)h0 | ((uint32_t)h1 << 16),
                          (uint32_t)h2 | ((uint32_t)h3 << 16));
    uint2 lp = make_uint2(
      (uint32_t)bf16u(vl.x - __bfloat162float(__ushort_as_bfloat16(h0))) |
      ((uint32_t)bf16u(vl.y - __bfloat162float(__ushort_as_bfloat16(h1))) << 16),
      (uint32_t)bf16u(vl.z - __bfloat162float(__ushort_as_bfloat16(h2))) |
      ((uint32_t)bf16u(vl.w - __bfloat162float(__ushort_as_bfloat16(h3))) << 16));
    *reinterpret_cast<uint2*>(reinterpret_cast<char*>(s.Wlh) + off) = hp;
    *reinterpret_cast<uint2*>(reinterpret_cast<char*>(s.Wll) + off) = lp;
    h0 = bf16u(vr.x); h1 = bf16u(vr.y); h2 = bf16u(vr.z); h3 = bf16u(vr.w);
    hp = make_uint2((uint32_t)h0 | ((uint32_t)h1 << 16),
                    (uint32_t)h2 | ((uint32_t)h3 << 16));
    lp = make_uint2(
      (uint32_t)bf16u(vr.x - __bfloat162float(__ushort_as_bfloat16(h0))) |
      ((uint32_t)bf16u(vr.y - __bfloat162float(__ushort_as_bfloat16(h1))) << 16),
      (uint32_t)bf16u(vr.z - __bfloat162float(__ushort_as_bfloat16(h2))) |
      ((uint32_t)bf16u(vr.w - __bfloat162float(__ushort_as_bfloat16(h3))) << 16));
    *reinterpret_cast<uint2*>(reinterpret_cast<char*>(s.Wrh) + off) = hp;
    *reinterpret_cast<uint2*>(reinterpret_cast<char*>(s.Wrl) + off) = lp;
  }
  for (int i = t; i < C; i += NTH) {
    s.bl[i] = bl[i]; s.br[i] = br[i]; s.att[i] = att[i]; s.bias[i] = bias[i];
  }
  const float sg  = 1.0f / (1.0f + __expf(-alpha[0]));
  const float oms = 1.0f - sg;
  __syncthreads();   // zero-fill of union must complete before LN writes

  // ---- LayerNorm -> Ah/Al (hi/lo bf16) ----
  for (int r = warp; r < MROWS; r += 16) {
    float v0 = xblk[r*C + lane],      v1 = xblk[r*C + lane + 32];
    float v2 = xblk[r*C + lane + 64], v3 = xblk[r*C + lane + 96];
    float sum = v0+v1+v2+v3, sq = v0*v0+v1*v1+v2*v2+v3*v3;
    #pragma unroll
    for (int o = 16; o > 0; o >>= 1) {
      sum += __shfl_xor_sync(0xffffffffu, sum, o);
      sq  += __shfl_xor_sync(0xffffffffu, sq,  o);
    }
    float mu = sum * (1.0f/C);
    float inv = rsqrtf(sq * (1.0f/C) - mu*mu + 1e-5f);
    #pragma unroll
    for (int q = 0; q < 4; ++q) {
      int cc = lane + 32*q;
      float vv = (q==0?v0:q==1?v1:q==2?v2:v3);
      float hval = (vv-mu)*inv*ln_gamma[cc] + ln_beta[cc];
      ushort hi = bf16u(hval);
      *reinterpret_cast<ushort*>(Ah_base + swzA(r, cc)) = hi;
      *reinterpret_cast<ushort*>(Al_base + swzA(r, cc)) =
          bf16u(hval - __bfloat162float(__ushort_as_bfloat16(hi)));
    }
  }

  const uint32_t aAh  = smem_u32(Ah_base), aAl  = smem_u32(Al_base);
  const uint32_t aWlh = smem_u32(s.Wlh), aWll = smem_u32(s.Wll);
  const uint32_t aWrh = smem_u32(s.Wrh), aWrl = smem_u32(s.Wrl);
  // lane decomposition for ldmatrix addressing
  const int rA = lane & 7;
  const int rowOffA = ((lane>>3)&1)*8 + rA;   // matrix row offset within m16
  const int chOffA  = (lane>>4);              // k-chunk offset (0/1)
  const int rB  = lane & 7;
  const int miB = (lane>>3)&1;
  const int n0w = warp * 8;                   // this warp's 8 output columns
  const int eM = lane >> 2;                   // epilogue lane mapping
  const int eN = 2*(lane & 3);

  #pragma unroll 1
  for (int layer = 0; layer < 4; ++layer) {
    __syncthreads();   // Ah/Al ready (LN or previous aggregation)

    float accL[NMT][4];
    float accR[NMT][4];
    #pragma unroll
    for (int mt = 0; mt < NMT; ++mt)
      #pragma unroll
      for (int q = 0; q < 4; ++q) { accL[mt][q] = 0.f; accR[mt][q] = 0.f; }

    #pragma unroll
    for (int ks = 0; ks < 8; ++ks) {
      uint32_t fAh[NMT][4], fAl[NMT][4];
      #pragma unroll
      for (int mt = 0; mt < NMT; ++mt) {
        uint32_t ar = (uint32_t)((mt*16 + rowOffA)*256 + (((2*ks + chOffA) ^ rA)<<4));
        ldsm4(fAh[mt], aAh + ar);
        ldsm4(fAl[mt], aAl + ar);
      }
      uint32_t boff = (uint32_t)((ks*16 + miB*8 + rB)*256 + (((n0w>>3) ^ rB)<<4));
      uint32_t bh[2], blo[2];
      ldsm2t(bh,  aWlh + boff);
      ldsm2t(blo, aWll + boff);
      #pragma unroll
      for (int mt = 0; mt < NMT; ++mt) {
        mma16816(accL[mt], fAh[mt], bh);
        mma16816(accL[mt], fAl[mt], bh);
        mma16816(accL[mt], fAh[mt], blo);
      }
      ldsm2t(bh,  aWrh + boff);
      ldsm2t(blo, aWrl + boff);
      #pragma unroll
      for (int mt = 0; mt < NMT; ++mt) {
        mma16816(accR[mt], fAh[mt], bh);
        mma16816(accR[mt], fAl[mt], bh);
        mma16816(accR[mt], fAh[mt], blo);
      }
    }
    __syncthreads();   // all GEMM reads of Ah/Al done before xrT overwrites them

    // ---- epilogue: fragments -> xlT / xrT-in-union (+bias) ----
    {
      int n0 = n0w + eN;
      float b0 = s.bl[n0], b1 = s.bl[n0+1];
      float c0 = s.br[n0], c1 = s.br[n0+1];
      #pragma unroll
      for (int mt = 0; mt < NMT; ++mt) {
        int m0 = mt*16 + eM;
        if (m0 < MROWS) {
          s.xlT[n0  ][m0] = accL[mt][0] + b0;
          s.xlT[n0+1][m0] = accL[mt][1] + b1;
          xrT[n0  ][m0] = accR[mt][0] + c0;
          xrT[n0+1][m0] = accR[mt][1] + c1;
        }
        if (m0+8 < MROWS) {
          s.xlT[n0  ][m0+8] = accL[mt][2] + b0;
          s.xlT[n0+1][m0+8] = accL[mt][3] + b1;
          xrT[n0  ][m0+8] = accR[mt][2] + c0;
          xrT[n0+1][m0+8] = accR[mt][3] + c1;
        }
      }
    }
    __syncthreads();

    // ---- edge logits: att . leaky_relu(xl[src] + xr[dst]) ----
    #pragma unroll
    for (int i = 0; i < 16; ++i) {          // 16 warps * 16 = 256 edges
      int eg = warp + 16*i;
      int g = eg >> 6, e = eg & 63;
      int gs = g*J + c_esrc[e];
      int gd = g*J + c_edst[e];
      float acc = 0.0f;
      #pragma unroll
      for (int q = 0; q < 4; ++q) {
        int cc = lane + 32*q;
        float v = s.xlT[cc][gs] + xrT[cc][gd];
        v = (v > 0.0f) ? v : 0.2f*v;
        acc += s.att[cc]*v;
      }
      #pragma unroll
      for (int o = 16; o > 0; o >>= 1)
        acc += __shfl_xor_sync(0xffffffffu, acc, o);
      if (lane == 0) s.logit[eg] = acc;
    }
    __syncthreads();

    // ---- segment softmax ----
    if (t < MROWS) {
      int g = t / J, n = t % J;
      const float* lg = &s.logit[g*NE];
      float m = -1e30f;
      #pragma unroll
      for (int e = 0; e < NE; ++e) if (EDST[e] == n) m = fmaxf(m, lg[e]);
      float d = 0.0f;
      #pragma unroll
      for (int e = 0; e < NE; ++e) if (EDST[e] == n) d += __expf(lg[e] - m);
      s.mx[t] = m; s.den[t] = d;
    }
    __syncthreads();
    if (t < GPB*NE) {
      int g = t >> 6, e = t & 63;
      int dn = g*J + c_edst[e];
      s.aw[t] = __expf(s.logit[t] - s.mx[dn]) / s.den[dn];
    }
    __syncthreads();

    // ---- aggregation + gate (all 512 threads); layer3 -> out = x + h ----
    {
      int g = t >> 7, cc = t & 127;
      float acc[J];
      #pragma unroll
      for (int n = 0; n < J; ++n) acc[n] = s.bias[cc];
      const float* ag = &s.aw[g*NE];
      #pragma unroll
      for (int e = 0; e < NE; ++e)
        acc[EDST[e]] += ag[e] * s.xlT[cc][g*J + ESRC[e]];
      #pragma unroll
      for (int n = 0; n < J; ++n) {
        int r = g*J + n;
        float v = acc[n];
        float xv = xblk[r*C + cc];
        if (layer > 0) v = oms*v + sg*xv;
        if (layer < 3) {
          ushort hi = bf16u(v);
          *reinterpret_cast<ushort*>(Ah_base + swzA(r, cc)) = hi;
          *reinterpret_cast<ushort*>(Al_base + swzA(r, cc)) =
              bf16u(v - __bfloat162float(__ushort_as_bfloat16(hi)));
        } else {
          out[(size_t)(node0 + r)*C + cc] = xv + v;
        }
      }
    }
  }
}

extern "C" void kernel_launch(void* const* d_in, const int* in_sizes, int n_in,
                              void* d_out, int out_size)
{
  const float* x        = (const float*)d_in[0];
  const float* ln_gamma = (const float*)d_in[1];
  const float* ln_beta  = (const float*)d_in[2];
  const float* alpha    = (const float*)d_in[3];
  const float* Wl       = (const float*)d_in[4];
  const float* bl       = (const float*)d_in[5];
  const float* Wr       = (const float*)d_in[6];
  const float* br       = (const float*)d_in[7];
  const float* att      = (const float*)d_in[8];
  const float* bias     = (const float*)d_in[9];
  (void)in_sizes; (void)n_in; (void)out_size;

  int smem = (int)sizeof(Smem) + 1024;
  (void)cudaFuncSetAttribute(rgat_hmma_kernel,
                             cudaFuncAttributeMaxDynamicSharedMemorySize, smem);
  rgat_hmma_kernel<<<NBLOCKS, NTH, smem>>>(
      x, ln_gamma, ln_beta, alpha, Wl, bl, Wr, br, att, bias, (float*)d_out);
}